// round 13
// baseline (speedup 1.0000x reference)
#include <cuda_runtime.h>
#include <cuda_bf16.h>
#include <cstdint>

#define N_SAMP 131072
#define NDIM_C 512
#define NCOMP_C 256
#define NCLASS_C 8
#define NBIN_C 100
#define SPB 37          // spline blocks per class (37*8=296 ~= 2 full waves)

// ---------------- device globals (no runtime allocation allowed) ----------
__device__ float g_scratch[(size_t)N_SAMP * NCOMP_C];          // data0 fp32
__device__ __nv_bfloat16 g_dAh[(size_t)N_SAMP * NCOMP_C];      // delta hi
__device__ __nv_bfloat16 g_dAl[(size_t)N_SAMP * NCOMP_C];      // delta lo
// GEMM1 B: [256][512] (wT transposed); GEMM2 B: [512][256] (native)
__device__ __nv_bfloat16 g_Bt_hi[NCOMP_C * NDIM_C];
__device__ __nv_bfloat16 g_Bt_lo[NCOMP_C * NDIM_C];
__device__ __nv_bfloat16 g_B2_hi[NDIM_C * NCOMP_C];
__device__ __nv_bfloat16 g_B2_lo[NDIM_C * NCOMP_C];
// class partition
__device__ int g_cnt[NCLASS_C];
__device__ int g_list[(size_t)NCLASS_C * N_SAMP];
// spline tables
__device__ float   g_xT[NCLASS_C * NBIN_C * NCOMP_C];           // [c][k][d]
// paired 32B records: [c][k][d] -> {(y0,d0,y1,d1),(x0,w,s,d0+d1-2s)}
__device__ float4  g_T[(size_t)NCLASS_C * (NBIN_C - 1) * NCOMP_C * 2];
__device__ uint8_t g_grid[NCLASS_C * 256 * NCOMP_C];            // [c][i][d]
__device__ float2  g_gs[NCLASS_C * NCOMP_C];                    // (gx0, ginv)

// ---------------------------------------------------------------------------
__device__ __forceinline__ uint32_t smem_u32(const void* p) {
    uint32_t a;
    asm("{ .reg .u64 t; cvta.to.shared.u64 t, %1; cvt.u32.u64 %0, t; }"
        : "=r"(a) : "l"(p));
    return a;
}
#define SWZ128(off) ((off) ^ (((off) >> 3) & 0x70))

__device__ __forceinline__ void cp16(uint32_t dst, const void* src) {
    asm volatile("cp.async.cg.shared.global [%0], [%1], 16;"
                 :: "r"(dst), "l"(src));
}
__device__ __forceinline__ void cp_commit() {
    asm volatile("cp.async.commit_group;" ::: "memory");
}
__device__ __forceinline__ void cp_wait0() {
    asm volatile("cp.async.wait_group 0;" ::: "memory");
}
__device__ __forceinline__ void cp_wait1() {
    asm volatile("cp.async.wait_group 1;" ::: "memory");
}
__device__ __forceinline__ void ldsm_x4(uint32_t* r, uint32_t addr) {
    asm volatile("ldmatrix.sync.aligned.m8n8.x4.shared.b16 {%0,%1,%2,%3}, [%4];"
                 : "=r"(r[0]), "=r"(r[1]), "=r"(r[2]), "=r"(r[3]) : "r"(addr));
}
__device__ __forceinline__ void mma_bf16(float* c, const uint32_t* a, const uint32_t* b) {
    asm volatile(
        "mma.sync.aligned.m16n8k16.row.col.f32.bf16.bf16.f32 "
        "{%0,%1,%2,%3}, {%4,%5,%6,%7}, {%8,%9}, {%0,%1,%2,%3};"
        : "+f"(c[0]), "+f"(c[1]), "+f"(c[2]), "+f"(c[3])
        : "r"(a[0]), "r"(a[1]), "r"(a[2]), "r"(a[3]), "r"(b[0]), "r"(b[1]));
}
__device__ __forceinline__ void split_bf16(float f, uint32_t& h, uint32_t& l) {
    __nv_bfloat16 hb = __float2bfloat16(f);
    __nv_bfloat16 lb = __float2bfloat16(f - __bfloat162float(hb));
    h = (uint32_t)__bfloat16_as_ushort(hb);
    l = (uint32_t)__bfloat16_as_ushort(lb);
}
// MUFU-free reciprocal (positive d): magic init + 3 Newton steps, rel ~1e-7
__device__ __forceinline__ float rcp_nr(float d) {
    float r = __uint_as_float(0x7EF311C3u - __float_as_uint(d));
    r = r * (2.0f - d * r);
    r = r * (2.0f - d * r);
    r = r * (2.0f - d * r);
    return r;
}
// extract exponent, renormalize mantissa to [1,2)
__device__ __forceinline__ void renorm(float& m, int& e) {
    uint32_t b = __float_as_uint(m);
    e += (int)((b >> 23) & 0xFFu) - 127;
    m = __uint_as_float((b & 0x807FFFFFu) | 0x3F800000u);
}

// ---------------------------------------------------------------------------
// prep kernels
// ---------------------------------------------------------------------------
__global__ void prep_split_w(const float* __restrict__ wT) {
    int i = blockIdx.x * 256 + threadIdx.x;      // over 512*256
    float v = wT[i];
    __nv_bfloat16 h = __float2bfloat16(v);
    __nv_bfloat16 l = __float2bfloat16(v - __bfloat162float(h));
    g_B2_hi[i] = h;  g_B2_lo[i] = l;
    int k = i >> 8, n = i & 255;
    g_Bt_hi[n * NDIM_C + k] = h;
    g_Bt_lo[n * NDIM_C + k] = l;
}

__global__ void k_zero() { if (threadIdx.x < NCLASS_C) g_cnt[threadIdx.x] = 0; }

__global__ void k_classify(const int* __restrict__ label) {
    __shared__ int h[NCLASS_C], base[NCLASS_C];
    const int n = blockIdx.x * 256 + threadIdx.x;
    if (threadIdx.x < NCLASS_C) h[threadIdx.x] = 0;
    __syncthreads();
    const int c = label[n];
    const int my = atomicAdd(&h[c], 1);
    __syncthreads();
    if (threadIdx.x < NCLASS_C)
        base[threadIdx.x] = atomicAdd(&g_cnt[threadIdx.x], h[threadIdx.x]);
    __syncthreads();
    g_list[(size_t)c * N_SAMP + base[c] + my] = n;
}

__global__ void k_xT(const float* __restrict__ kx) {
    int i = blockIdx.x * 256 + threadIdx.x;       // 8*100*256
    int d = i & 255, rest = i >> 8;
    int k = rest % NBIN_C, c = rest / NBIN_C;
    g_xT[(c * NBIN_C + k) * NCOMP_C + d] = kx[((size_t)(c * NCOMP_C + d)) * NBIN_C + k];
}

__global__ void k_tabT(const float* __restrict__ kx,
                       const float* __restrict__ ky,
                       const float* __restrict__ kd) {
    int i = blockIdx.x * 256 + threadIdx.x;       // 8*99*256
    int d = i & 255, rest = i >> 8;
    int k = rest % (NBIN_C - 1), c = rest / (NBIN_C - 1);
    size_t src = ((size_t)c * NCOMP_C + d) * NBIN_C + k;
    float x0 = kx[src], x1 = kx[src + 1];
    float y0 = ky[src], y1 = ky[src + 1];
    float d0 = kd[src], d1 = kd[src + 1];
    float w = x1 - x0;
    float s = (y1 - y0) / w;                       // reference-matching div
    size_t o = (((size_t)c * (NBIN_C - 1) + k) * NCOMP_C + d) * 2;
    g_T[o]     = make_float4(y0, d0, y1, d1);
    g_T[o + 1] = make_float4(x0, w, s, d0 + d1 - 2.0f * s);
}

// per (c,d): build 256-bin acceleration grid (two-pointer over knots)
__global__ void k_grid(const float* __restrict__ kx) {
    const int c = blockIdx.x, d = threadIdx.x;
    const float* xr = kx + ((size_t)(c * NCOMP_C + d)) * NBIN_C;
    float x0 = xr[0], x99 = xr[NBIN_C - 1];
    float R = x99 - x0;
    g_gs[c * NCOMP_C + d] = make_float2(x0, 256.0f / R);
    const float step = R * (1.0f / 256.0f);
    int k = 0;
    for (int i = 0; i < 256; i++) {
        float e = x0 + (float)i * step - 1e-4f;    // safety margin
        while (k < NBIN_C && xr[k] < e) k++;
        g_grid[(c * 256 + i) * NCOMP_C + d] = (uint8_t)k;
    }
}

// ---------------------------------------------------------------------------
// GEMM1: C[M,256] = A(fp32, converted in-kernel) @ B(bf16 hi/lo)^T  (unchanged)
// ---------------------------------------------------------------------------
static constexpr int G1_BSTAGE = 32768;
static constexpr int G1_ACVT   = 65536;
static constexpr int G1_SMEM   = 98304;

__global__ __launch_bounds__(512, 1)
void gemm_cvtA(const float* __restrict__ A,
               const __nv_bfloat16* __restrict__ Bhi,
               const __nv_bfloat16* __restrict__ Blo,
               float* __restrict__ C)
{
    constexpr int KTOT = NDIM_C, NOUT = NCOMP_C;
    extern __shared__ char smem[];
    const uint32_t sb = smem_u32(smem);
    const int tid  = threadIdx.x;
    const int lane = tid & 31;
    const int wid  = tid >> 5;
    const int wm   = wid & 3;
    const int wn   = wid >> 2;
    const int row0 = blockIdx.y * 128;
    const int n0   = blockIdx.x * 128;

    auto loadB = [&](int ch, int s) {
        const uint32_t st = sb + s * G1_BSTAGE;
        const int k0 = ch * 64;
        #pragma unroll
        for (int i = 0; i < 2; i++) {
            int u = i * 512 + tid;
            int r = u >> 3, u8 = (u & 7) << 3;
            uint32_t off = SWZ128((uint32_t)(r * 128 + u8 * 2));
            size_t g = (size_t)(n0 + r) * KTOT + k0 + u8;
            cp16(st + off,         Bhi + g);
            cp16(st + 16384 + off, Blo + g);
        }
        cp_commit();
    };
    auto loadA = [&](int ch, float4* rg) {
        const int k0 = ch * 64;
        #pragma unroll
        for (int i = 0; i < 2; i++) {
            int u = i * 512 + tid;
            int r = u >> 3, c8 = (u & 7) << 3;
            const float* p = A + (size_t)(row0 + r) * KTOT + k0 + c8;
            rg[i * 2]     = *reinterpret_cast<const float4*>(p);
            rg[i * 2 + 1] = *reinterpret_cast<const float4*>(p + 4);
        }
    };
    auto convertA = [&](const float4* rg) {
        #pragma unroll
        for (int i = 0; i < 2; i++) {
            int u = i * 512 + tid;
            int r = u >> 3, c8 = (u & 7) << 3;
            float f[8] = {rg[i*2].x, rg[i*2].y, rg[i*2].z, rg[i*2].w,
                          rg[i*2+1].x, rg[i*2+1].y, rg[i*2+1].z, rg[i*2+1].w};
            uint32_t hw[8], lw[8];
            #pragma unroll
            for (int j = 0; j < 8; j++) split_bf16(f[j], hw[j], lw[j]);
            uint4 hv = {hw[0] | (hw[1] << 16), hw[2] | (hw[3] << 16),
                        hw[4] | (hw[5] << 16), hw[6] | (hw[7] << 16)};
            uint4 lv = {lw[0] | (lw[1] << 16), lw[2] | (lw[3] << 16),
                        lw[4] | (lw[5] << 16), lw[6] | (lw[7] << 16)};
            uint32_t off = SWZ128((uint32_t)(r * 128 + c8 * 2));
            *reinterpret_cast<uint4*>(smem + G1_ACVT + off)        = hv;
            *reinterpret_cast<uint4*>(smem + G1_ACVT + 16384 + off) = lv;
        }
    };

    float acc[2][4][4];
    #pragma unroll
    for (int i = 0; i < 2; i++)
        #pragma unroll
        for (int j = 0; j < 4; j++)
            #pragma unroll
            for (int v = 0; v < 4; v++) acc[i][j][v] = 0.0f;

    constexpr int NCH = KTOT / 64;
    float4 areg[4], areg2[4];
    loadB(0, 0);
    loadA(0, areg);

    for (int ch = 0; ch < NCH; ch++) {
        const int s = ch & 1;
        if (ch + 1 < NCH) {
            loadB(ch + 1, s ^ 1);
            loadA(ch + 1, areg2);
        }
        convertA(areg);
        if (ch + 1 < NCH) cp_wait1(); else cp_wait0();
        __syncthreads();

        const uint32_t st = sb + s * G1_BSTAGE;
        const uint32_t sa = sb + G1_ACVT;
        #pragma unroll
        for (int ks = 0; ks < 4; ks++) {
            const int Ck = ks * 16;
            uint32_t ah[2][4], al[2][4];
            #pragma unroll
            for (int mt = 0; mt < 2; mt++) {
                uint32_t aoff = SWZ128((uint32_t)(
                    (wm * 32 + mt * 16 + (lane & 15)) * 128 + (Ck + (lane >> 4) * 8) * 2));
                ldsm_x4(ah[mt], sa + aoff);
                ldsm_x4(al[mt], sa + 16384 + aoff);
            }
            #pragma unroll
            for (int p = 0; p < 2; p++) {
                uint32_t boff = SWZ128((uint32_t)(
                    (wn * 32 + p * 16 + ((lane >> 4) << 3) + (lane & 7)) * 128 +
                    (Ck + ((lane >> 3) & 1) * 8) * 2));
                uint32_t bh4[4], bl4[4];
                ldsm_x4(bh4, st + boff);
                ldsm_x4(bl4, st + 16384 + boff);
                #pragma unroll
                for (int hf = 0; hf < 2; hf++) {
                    const int nt = 2 * p + hf;
                    const uint32_t* bh = bh4 + 2 * hf;
                    const uint32_t* bl = bl4 + 2 * hf;
                    #pragma unroll
                    for (int mt = 0; mt < 2; mt++) {
                        mma_bf16(acc[mt][nt], ah[mt], bh);
                        mma_bf16(acc[mt][nt], ah[mt], bl);
                        mma_bf16(acc[mt][nt], al[mt], bh);
                    }
                }
            }
        }
        #pragma unroll
        for (int i = 0; i < 4; i++) areg[i] = areg2[i];
        __syncthreads();
    }

    const int gr = lane >> 2;
    const int cp = (lane & 3) * 2;
    #pragma unroll
    for (int mt = 0; mt < 2; mt++) {
        #pragma unroll
        for (int nt = 0; nt < 4; nt++) {
            int row = row0 + wm * 32 + mt * 16 + gr;
            int col = n0 + wn * 32 + nt * 8 + cp;
            size_t g0 = (size_t)row * NOUT + col;
            size_t g1 = (size_t)(row + 8) * NOUT + col;
            *reinterpret_cast<float2*>(C + g0) = make_float2(acc[mt][nt][0], acc[mt][nt][1]);
            *reinterpret_cast<float2*>(C + g1) = make_float2(acc[mt][nt][2], acc[mt][nt][3]);
        }
    }
}

// ---------------------------------------------------------------------------
// GEMM2: out = data + delta @ wT.T  (unchanged)
// ---------------------------------------------------------------------------
static constexpr int G2_STAGE = 65536;
static constexpr int G2_SMEM  = 2 * G2_STAGE;

__global__ __launch_bounds__(512, 1)
void gemm_bf16(const __nv_bfloat16* __restrict__ Ahi,
               const __nv_bfloat16* __restrict__ Alo,
               const __nv_bfloat16* __restrict__ Bhi,
               const __nv_bfloat16* __restrict__ Blo,
               const float* __restrict__ Csrc,
               float* __restrict__ C)
{
    constexpr int KTOT = NCOMP_C, NOUT = NDIM_C;
    extern __shared__ char smem[];
    const uint32_t sb = smem_u32(smem);
    const int tid  = threadIdx.x;
    const int lane = tid & 31;
    const int wid  = tid >> 5;
    const int wm   = wid & 3;
    const int wn   = wid >> 2;
    const int row0 = blockIdx.y * 128;
    const int n0   = blockIdx.x * 128;

    auto load_stage = [&](int ch, int s) {
        const uint32_t st = sb + s * G2_STAGE;
        const int k0 = ch * 64;
        #pragma unroll
        for (int i = 0; i < 2; i++) {
            int u = i * 512 + tid;
            int r = u >> 3, u8 = (u & 7) << 3;
            uint32_t off = SWZ128((uint32_t)(r * 128 + u8 * 2));
            size_t ga = (size_t)(row0 + r) * KTOT + k0 + u8;
            size_t gb = (size_t)(n0 + r) * KTOT + k0 + u8;
            cp16(st + off,         Ahi + ga);
            cp16(st + 16384 + off, Alo + ga);
            cp16(st + 32768 + off, Bhi + gb);
            cp16(st + 49152 + off, Blo + gb);
        }
        cp_commit();
    };

    float acc[2][4][4];
    #pragma unroll
    for (int i = 0; i < 2; i++)
        #pragma unroll
        for (int j = 0; j < 4; j++)
            #pragma unroll
            for (int v = 0; v < 4; v++) acc[i][j][v] = 0.0f;

    constexpr int NCH = KTOT / 64;
    load_stage(0, 0);

    for (int ch = 0; ch < NCH; ch++) {
        const int s = ch & 1;
        if (ch + 1 < NCH) load_stage(ch + 1, s ^ 1);
        if (ch + 1 < NCH) cp_wait1(); else cp_wait0();
        __syncthreads();

        const uint32_t st = sb + s * G2_STAGE;
        #pragma unroll
        for (int ks = 0; ks < 4; ks++) {
            const int Ck = ks * 16;
            uint32_t ah[2][4], al[2][4];
            #pragma unroll
            for (int mt = 0; mt < 2; mt++) {
                uint32_t aoff = SWZ128((uint32_t)(
                    (wm * 32 + mt * 16 + (lane & 15)) * 128 + (Ck + (lane >> 4) * 8) * 2));
                ldsm_x4(ah[mt], st + aoff);
                ldsm_x4(al[mt], st + 16384 + aoff);
            }
            #pragma unroll
            for (int p = 0; p < 2; p++) {
                uint32_t boff = SWZ128((uint32_t)(
                    (wn * 32 + p * 16 + ((lane >> 4) << 3) + (lane & 7)) * 128 +
                    (Ck + ((lane >> 3) & 1) * 8) * 2));
                uint32_t bh4[4], bl4[4];
                ldsm_x4(bh4, st + 32768 + boff);
                ldsm_x4(bl4, st + 49152 + boff);
                #pragma unroll
                for (int hf = 0; hf < 2; hf++) {
                    const int nt = 2 * p + hf;
                    const uint32_t* bh = bh4 + 2 * hf;
                    const uint32_t* bl = bl4 + 2 * hf;
                    #pragma unroll
                    for (int mt = 0; mt < 2; mt++) {
                        mma_bf16(acc[mt][nt], ah[mt], bh);
                        mma_bf16(acc[mt][nt], ah[mt], bl);
                        mma_bf16(acc[mt][nt], al[mt], bh);
                    }
                }
            }
        }
        __syncthreads();
    }

    const int gr = lane >> 2;
    const int cp = (lane & 3) * 2;
    #pragma unroll
    for (int mt = 0; mt < 2; mt++) {
        #pragma unroll
        for (int nt = 0; nt < 4; nt++) {
            int row = row0 + wm * 32 + mt * 16 + gr;
            int col = n0 + wn * 32 + nt * 8 + cp;
            size_t g0 = (size_t)row * NOUT + col;
            size_t g1 = (size_t)(row + 8) * NOUT + col;
            float2 s0 = *reinterpret_cast<const float2*>(Csrc + g0);
            float2 s1 = *reinterpret_cast<const float2*>(Csrc + g1);
            *reinterpret_cast<float2*>(C + g0) =
                make_float2(acc[mt][nt][0] + s0.x, acc[mt][nt][1] + s0.y);
            *reinterpret_cast<float2*>(C + g1) =
                make_float2(acc[mt][nt][2] + s1.x, acc[mt][nt][3] + s1.y);
        }
    }
}

// ---------------------------------------------------------------------------
// Spline v2: warp-per-sample, barrier-free, MUFU-free (1 log2f per sample).
// smem: fp32 x-knots [100][256] + u8 accel grid [256][256] + gs float2[256].
// Each warp: 8 chunks of 32 comps per sample; grid lookup + <=4 exact scan
// steps; one 32B table gather per element; exponent-tracked product for logj.
// ---------------------------------------------------------------------------
static constexpr int SP_XS   = 0;                  // 102400 B
static constexpr int SP_GRID = 102400;             // 65536 B
static constexpr int SP_GS   = 167936;             // 2048 B
static constexpr int SPLINE_SMEM = 169984;

__global__ __launch_bounds__(512, 1)
void spline2(const float* __restrict__ x_in, float* __restrict__ logj)
{
    extern __shared__ char sm[];
    float*   xs   = reinterpret_cast<float*>(sm + SP_XS);
    uint8_t* grid = reinterpret_cast<uint8_t*>(sm + SP_GRID);
    float2*  gs   = reinterpret_cast<float2*>(sm + SP_GS);

    const int c   = blockIdx.y;
    const int tid = threadIdx.x;
    const int w   = tid >> 5, lane = tid & 31;

    // table loads (coalesced)
    {
        const float4* src = reinterpret_cast<const float4*>(
            g_xT + (size_t)c * NBIN_C * NCOMP_C);
        float4* dst = reinterpret_cast<float4*>(xs);
        for (int i = tid; i < NBIN_C * NCOMP_C / 4; i += 512) dst[i] = src[i];
        const uint4* gsrc = reinterpret_cast<const uint4*>(
            g_grid + (size_t)c * 256 * NCOMP_C);
        uint4* gdst = reinterpret_cast<uint4*>(grid);
        #pragma unroll
        for (int i = 0; i < 8; i++) gdst[i * 512 + tid] = gsrc[i * 512 + tid];
        if (tid < NCOMP_C) gs[tid] = g_gs[c * NCOMP_C + tid];
    }
    __syncthreads();

    const int cnt = g_cnt[c];
    const int* lst = g_list + (size_t)c * N_SAMP;
    const float4* T = g_T + (size_t)c * (NBIN_C - 1) * NCOMP_C * 2;

    for (int i = blockIdx.x * 16 + w; i < cnt; i += SPB * 16) {
        const int n = lst[i];
        const float* xrow = x_in + (size_t)n * NCOMP_C;

        float xv[8];
        int   kk[8];
        // load + search (independent chains, ILP-8)
        #pragma unroll
        for (int ch = 0; ch < 8; ch++) {
            const int dd = ch * 32 + lane;
            const float x = __ldg(xrow + dd);
            xv[ch] = x;
            const float2 g2 = gs[dd];
            float t = (x - g2.x) * g2.y;
            int bi = __float2int_rz(fminf(fmaxf(t, 0.0f), 255.0f));
            int k = (int)grid[bi * NCOMP_C + dd];
            #pragma unroll
            for (int st = 0; st < 4; st++) {
                float kv = xs[min(k, NBIN_C - 1) * NCOMP_C + dd];
                k += (k < NBIN_C && kv < x) ? 1 : 0;
            }
            kk[ch] = k;              // = searchsorted idx in [0,100]
        }

        float m = 1.0f;
        int   e = 0;
        // eval + store (per-chunk; table gather = one 32B sector)
        #pragma unroll
        for (int ch = 0; ch < 8; ch++) {
            const int dd = ch * 32 + lane;
            const int idx = kk[ch];
            const int kb = (idx == 0) ? 0 : ((idx == NBIN_C) ? NBIN_C - 2 : idx - 1);
            const float4* Tp = T + ((size_t)kb * NCOMP_C + dd) * 2;
            const float4 a = __ldg(Tp);       // (y0,d0,y1,d1)
            const float4 b = __ldg(Tp + 1);   // (x0,w,s,c3)
            const float x = xv[ch];
            float y, r;
            if (idx == 0) {
                y = a.x + a.y * (x - b.x);           r = a.y;
            } else if (idx == NBIN_C) {
                y = a.z + a.w * (x - (b.x + b.y));   r = a.w;
            } else {
                const float winv = rcp_nr(b.y);
                float xi = fminf(fmaxf((x - b.x) * winv, 0.0f), 1.0f);
                const float xi1 = 1.0f - xi;
                const float t   = xi * xi1;
                const float denom = b.z + b.w * t;
                const float rd  = rcp_nr(denom);
                const float num = b.z * xi * xi + a.y * t;
                y = a.x + (a.z - a.x) * num * rd;
                const float num2 = a.w * xi * xi + 2.0f * b.z * t + a.y * xi1 * xi1;
                const float sr = b.z * rd;
                r = sr * sr * num2;                  // = s^2 * num2 / denom^2
            }
            const float dta = y - x;
            uint32_t hh, ll;
            split_bf16(dta, hh, ll);
            g_dAh[(size_t)n * NCOMP_C + dd] = __ushort_as_bfloat16((unsigned short)hh);
            g_dAl[(size_t)n * NCOMP_C + dd] = __ushort_as_bfloat16((unsigned short)ll);
            m *= r;
            renorm(m, e);
        }

        // cross-lane product combine (xor tree, deterministic)
        #pragma unroll
        for (int off = 16; off; off >>= 1) {
            m *= __shfl_xor_sync(0xffffffffu, m, off);
            e += __shfl_xor_sync(0xffffffffu, e, off);
            renorm(m, e);
        }
        if (lane == 0)
            logj[n] = ((float)e + __log2f(m)) * 0.69314718055994531f;
    }
}

// ---------------------------------------------------------------------------
extern "C" void kernel_launch(void* const* d_in, const int* in_sizes, int n_in,
                              void* d_out, int out_size)
{
    const float* data  = (const float*)d_in[0];   // (N, 512)
    const float* wT    = (const float*)d_in[1];   // (512, 256)
    const float* kx    = (const float*)d_in[2];
    const float* ky    = (const float*)d_in[3];
    const float* kd    = (const float*)d_in[4];
    const int*   label = (const int*)d_in[5];

    float* out  = (float*)d_out;
    float* logj = out + (size_t)N_SAMP * NDIM_C;

    float* scratch = nullptr;
    cudaGetSymbolAddress((void**)&scratch, g_scratch);
    __nv_bfloat16 *dah, *dal, *bt_hi, *bt_lo, *b2_hi, *b2_lo;
    cudaGetSymbolAddress((void**)&dah, g_dAh);
    cudaGetSymbolAddress((void**)&dal, g_dAl);
    cudaGetSymbolAddress((void**)&bt_hi, g_Bt_hi);
    cudaGetSymbolAddress((void**)&bt_lo, g_Bt_lo);
    cudaGetSymbolAddress((void**)&b2_hi, g_B2_hi);
    cudaGetSymbolAddress((void**)&b2_lo, g_B2_lo);

    cudaFuncSetAttribute(gemm_cvtA,
                         cudaFuncAttributeMaxDynamicSharedMemorySize, G1_SMEM);
    cudaFuncSetAttribute(gemm_bf16,
                         cudaFuncAttributeMaxDynamicSharedMemorySize, G2_SMEM);
    cudaFuncSetAttribute(spline2,
                         cudaFuncAttributeMaxDynamicSharedMemorySize, SPLINE_SMEM);

    // prep
    prep_split_w<<<(NDIM_C * NCOMP_C) / 256, 256>>>(wT);
    k_zero<<<1, 32>>>();
    k_classify<<<N_SAMP / 256, 256>>>(label);
    k_xT<<<(NCLASS_C * NBIN_C * NCOMP_C) / 256, 256>>>(kx);
    k_tabT<<<(NCLASS_C * (NBIN_C - 1) * NCOMP_C) / 256, 256>>>(kx, ky, kd);
    k_grid<<<NCLASS_C, NCOMP_C>>>(kx);

    // 1) data0 = data @ wT   (M=131072, N=256, K=512); A converted in-kernel
    gemm_cvtA<<<dim3(NCOMP_C / 128, N_SAMP / 128), 512, G1_SMEM>>>(
        data, bt_hi, bt_lo, scratch);

    // 2) spline: delta (bf16 hi/lo) + logj
    spline2<<<dim3(SPB, NCLASS_C), 512, SPLINE_SMEM>>>(scratch, logj);

    // 3) out = data + delta @ wT.T  (M=131072, N=512, K=256)
    gemm_bf16<<<dim3(NDIM_C / 128, N_SAMP / 128), 512, G2_SMEM>>>(
        dah, dal, b2_hi, b2_lo, data, out);
}

// round 15
// speedup vs baseline: 1.3240x; 1.3240x over previous
#include <cuda_runtime.h>
#include <cuda_bf16.h>
#include <cstdint>

#define N_SAMP 131072
#define NDIM_C 512
#define NCOMP_C 256
#define NCLASS_C 8
#define NBIN_C 100
#define SPB 64          // spline blocks per class

// ---------------- device globals (no runtime allocation allowed) ----------
__device__ float g_scratch[(size_t)N_SAMP * NCOMP_C];          // data0 fp32
__device__ __nv_bfloat16 g_dAh[(size_t)N_SAMP * NCOMP_C];      // delta hi
__device__ __nv_bfloat16 g_dAl[(size_t)N_SAMP * NCOMP_C];      // delta lo
// GEMM1 B: [256][512] (wT transposed); GEMM2 B: [512][256] (native)
__device__ __nv_bfloat16 g_Bt_hi[NCOMP_C * NDIM_C];
__device__ __nv_bfloat16 g_Bt_lo[NCOMP_C * NDIM_C];
__device__ __nv_bfloat16 g_B2_hi[NDIM_C * NCOMP_C];
__device__ __nv_bfloat16 g_B2_lo[NDIM_C * NCOMP_C];
// class partition
__device__ int g_cnt[NCLASS_C];
__device__ int g_list[(size_t)NCLASS_C * N_SAMP];
// transposed knot tables: g_xT[c][k][d]; g_ydp[c][k][d] = (y_k,d_k,y_k+1,d_k+1)
__device__ float  g_xT[NCLASS_C * NBIN_C * NCOMP_C];
__device__ float4 g_ydp[NCLASS_C * (NBIN_C - 1) * NCOMP_C];

// ---------------------------------------------------------------------------
__device__ __forceinline__ uint32_t smem_u32(const void* p) {
    uint32_t a;
    asm("{ .reg .u64 t; cvta.to.shared.u64 t, %1; cvt.u32.u64 %0, t; }"
        : "=r"(a) : "l"(p));
    return a;
}
#define SWZ128(off) ((off) ^ (((off) >> 3) & 0x70))

__device__ __forceinline__ void cp16(uint32_t dst, const void* src) {
    asm volatile("cp.async.cg.shared.global [%0], [%1], 16;"
                 :: "r"(dst), "l"(src));
}
__device__ __forceinline__ void cp_commit() {
    asm volatile("cp.async.commit_group;" ::: "memory");
}
__device__ __forceinline__ void cp_wait0() {
    asm volatile("cp.async.wait_group 0;" ::: "memory");
}
__device__ __forceinline__ void ldsm_x4(uint32_t* r, uint32_t addr) {
    asm volatile("ldmatrix.sync.aligned.m8n8.x4.shared.b16 {%0,%1,%2,%3}, [%4];"
                 : "=r"(r[0]), "=r"(r[1]), "=r"(r[2]), "=r"(r[3]) : "r"(addr));
}
__device__ __forceinline__ void mma_bf16(float* c, const uint32_t* a, const uint32_t* b) {
    asm volatile(
        "mma.sync.aligned.m16n8k16.row.col.f32.bf16.bf16.f32 "
        "{%0,%1,%2,%3}, {%4,%5,%6,%7}, {%8,%9}, {%0,%1,%2,%3};"
        : "+f"(c[0]), "+f"(c[1]), "+f"(c[2]), "+f"(c[3])
        : "r"(a[0]), "r"(a[1]), "r"(a[2]), "r"(a[3]), "r"(b[0]), "r"(b[1]));
}
__device__ __forceinline__ void split_bf16(float f, uint32_t& h, uint32_t& l) {
    __nv_bfloat16 hb = __float2bfloat16(f);
    __nv_bfloat16 lb = __float2bfloat16(f - __bfloat162float(hb));
    h = (uint32_t)__bfloat16_as_ushort(hb);
    l = (uint32_t)__bfloat16_as_ushort(lb);
}

// ---------------------------------------------------------------------------
// prep: fused wT split + knot table transpose (single launch)
// ---------------------------------------------------------------------------
__global__ void k_prep(const float* __restrict__ wT,
                       const float* __restrict__ kx,
                       const float* __restrict__ ky,
                       const float* __restrict__ kd) {
    const int b = blockIdx.x;
    if (b < 512) {
        int i = b * 256 + threadIdx.x;           // over 512*256
        float v = wT[i];
        __nv_bfloat16 h = __float2bfloat16(v);
        __nv_bfloat16 l = __float2bfloat16(v - __bfloat162float(h));
        g_B2_hi[i] = h;  g_B2_lo[i] = l;
        int k = i >> 8, n = i & 255;
        g_Bt_hi[n * NDIM_C + k] = h;
        g_Bt_lo[n * NDIM_C + k] = l;
    } else {
        int i = (b - 512) * 256 + threadIdx.x;   // over 8*100*256
        int d = i & 255, rest = i >> 8;
        int k = rest % NBIN_C, c = rest / NBIN_C;
        size_t src = ((size_t)c * NCOMP_C + d) * NBIN_C + k;
        g_xT[(c * NBIN_C + k) * NCOMP_C + d] = kx[src];
        if (k < NBIN_C - 1)
            g_ydp[((size_t)c * (NBIN_C - 1) + k) * NCOMP_C + d] =
                make_float4(ky[src], kd[src], ky[src + 1], kd[src + 1]);
    }
}

__global__ void k_zero() { if (threadIdx.x < NCLASS_C) g_cnt[threadIdx.x] = 0; }

__global__ void k_classify(const int* __restrict__ label) {
    __shared__ int h[NCLASS_C], base[NCLASS_C];
    const int n = blockIdx.x * 256 + threadIdx.x;
    if (threadIdx.x < NCLASS_C) h[threadIdx.x] = 0;
    __syncthreads();
    const int c = label[n];
    const int my = atomicAdd(&h[c], 1);
    __syncthreads();
    if (threadIdx.x < NCLASS_C)
        base[threadIdx.x] = atomicAdd(&g_cnt[threadIdx.x], h[threadIdx.x]);
    __syncthreads();
    g_list[(size_t)c * N_SAMP + base[c] + my] = n;
}

// ---------------------------------------------------------------------------
// GEMM1: scratch[M,256] = data(fp32) @ wT  — CTA tile 128x256 (all of N),
// 256 threads = 8 warps (2M x 4N), warp tile 64x64, K-chunk 64, NCH=8.
// A staged fp32 via cp.async (2x32KB), converted smem->smem to bf16 hi/lo;
// B bf16 hi/lo double-buffered (2x64KB). 224KB smem.
// Pipeline: wait(current, = wait_group 0 since exactly 1 pending) ->
// convert -> issue(next) -> compute. Loads overlap compute.
// ---------------------------------------------------------------------------
static constexpr int G1_B0   = 0;          // B stages: 2 x 65536 (hi 32K | lo 32K)
static constexpr int G1_AF   = 131072;     // A fp32 stages: 2 x 32768
static constexpr int G1_ACVT = 196608;     // Ahi 16K | Alo 16K
static constexpr int G1_SMEM = 229376;     // 224 KB

__global__ __launch_bounds__(256, 1)
void gemm1_cvt(const float* __restrict__ A,
               const __nv_bfloat16* __restrict__ Bhi,
               const __nv_bfloat16* __restrict__ Blo,
               float* __restrict__ C)
{
    constexpr int KTOT = NDIM_C, NOUT = NCOMP_C, NCH = KTOT / 64;
    extern __shared__ char smem[];
    const uint32_t sb = smem_u32(smem);
    const int tid  = threadIdx.x;
    const int lane = tid & 31;
    const int wid  = tid >> 5;
    const int wm   = wid & 1;            // 2 warps along M (64 rows)
    const int wn   = wid >> 1;           // 4 warps along N (64 cols)
    const int row0 = blockIdx.y * 128;

    auto issue_loads = [&](int ch, int s) {
        const int k0 = ch * 64;
        const uint32_t stB = sb + G1_B0 + s * 65536;
        #pragma unroll
        for (int i = 0; i < 8; i++) {               // B: 2048 units of 8 bf16
            int u = i * 256 + tid;
            int r = u >> 3, u8 = (u & 7) << 3;      // r in [0,256)
            uint32_t off = SWZ128((uint32_t)(r * 128 + u8 * 2));
            size_t g = (size_t)r * KTOT + k0 + u8;
            cp16(stB + off,         Bhi + g);
            cp16(stB + 32768 + off, Blo + g);
        }
        const uint32_t stA = sb + G1_AF + s * 32768;
        #pragma unroll
        for (int i = 0; i < 8; i++) {               // A fp32: 2048 units of 4 f
            int u = i * 256 + tid;
            int r = u >> 4, c4 = (u & 15) << 2;     // r in [0,128)
            cp16(stA + u * 16, A + (size_t)(row0 + r) * KTOT + k0 + c4);
        }
        cp_commit();
    };
    auto convertA = [&](int s) {
        const float4* af = reinterpret_cast<const float4*>(smem + G1_AF + s * 32768);
        #pragma unroll
        for (int i = 0; i < 4; i++) {               // 1024 units of 8 floats
            int u = i * 256 + tid;
            int r = u >> 3, c8 = (u & 7) << 3;
            float4 v0 = af[u * 2], v1 = af[u * 2 + 1];
            float f[8] = {v0.x, v0.y, v0.z, v0.w, v1.x, v1.y, v1.z, v1.w};
            uint32_t hw[8], lw[8];
            #pragma unroll
            for (int j = 0; j < 8; j++) split_bf16(f[j], hw[j], lw[j]);
            uint4 hv = {hw[0] | (hw[1] << 16), hw[2] | (hw[3] << 16),
                        hw[4] | (hw[5] << 16), hw[6] | (hw[7] << 16)};
            uint4 lv = {lw[0] | (lw[1] << 16), lw[2] | (lw[3] << 16),
                        lw[4] | (lw[5] << 16), lw[6] | (lw[7] << 16)};
            uint32_t off = SWZ128((uint32_t)(r * 128 + c8 * 2));
            *reinterpret_cast<uint4*>(smem + G1_ACVT + off)         = hv;
            *reinterpret_cast<uint4*>(smem + G1_ACVT + 16384 + off) = lv;
        }
    };

    float acc[4][8][4];
    #pragma unroll
    for (int i = 0; i < 4; i++)
        #pragma unroll
        for (int j = 0; j < 8; j++)
            #pragma unroll
            for (int v = 0; v < 4; v++) acc[i][j][v] = 0.0f;

    issue_loads(0, 0);

    for (int ch = 0; ch < NCH; ch++) {
        const int s = ch & 1;
        cp_wait0();                      // exactly 1 pending group = current chunk
        __syncthreads();                 // data visible; prior-stage reads done
        convertA(s);
        if (ch + 1 < NCH) issue_loads(ch + 1, s ^ 1);
        __syncthreads();                 // Acvt visible

        const uint32_t stB = sb + G1_B0 + s * 65536;
        const uint32_t sa  = sb + G1_ACVT;
        #pragma unroll
        for (int ks = 0; ks < 4; ks++) {
            const int Ck = ks * 16;
            uint32_t ah[4][4], al[4][4];
            #pragma unroll
            for (int mt = 0; mt < 4; mt++) {
                uint32_t aoff = SWZ128((uint32_t)(
                    (wm * 64 + mt * 16 + (lane & 15)) * 128 + (Ck + (lane >> 4) * 8) * 2));
                ldsm_x4(ah[mt], sa + aoff);
                ldsm_x4(al[mt], sa + 16384 + aoff);
            }
            #pragma unroll
            for (int p = 0; p < 4; p++) {
                uint32_t boff = SWZ128((uint32_t)(
                    (wn * 64 + p * 16 + ((lane >> 4) << 3) + (lane & 7)) * 128 +
                    (Ck + ((lane >> 3) & 1) * 8) * 2));
                uint32_t bh4[4], bl4[4];
                ldsm_x4(bh4, stB + boff);
                ldsm_x4(bl4, stB + 32768 + boff);
                #pragma unroll
                for (int hf = 0; hf < 2; hf++) {
                    const int nt = 2 * p + hf;
                    const uint32_t* bh = bh4 + 2 * hf;
                    const uint32_t* bl = bl4 + 2 * hf;
                    #pragma unroll
                    for (int mt = 0; mt < 4; mt++) {
                        mma_bf16(acc[mt][nt], ah[mt], bh);
                        mma_bf16(acc[mt][nt], ah[mt], bl);
                        mma_bf16(acc[mt][nt], al[mt], bh);
                    }
                }
            }
        }
    }

    const int gr = lane >> 2;
    const int cp = (lane & 3) * 2;
    #pragma unroll
    for (int mt = 0; mt < 4; mt++) {
        #pragma unroll
        for (int nt = 0; nt < 8; nt++) {
            int row = row0 + wm * 64 + mt * 16 + gr;
            int col = wn * 64 + nt * 8 + cp;
            size_t g0 = (size_t)row * NOUT + col;
            size_t g1 = (size_t)(row + 8) * NOUT + col;
            *reinterpret_cast<float2*>(C + g0) = make_float2(acc[mt][nt][0], acc[mt][nt][1]);
            *reinterpret_cast<float2*>(C + g1) = make_float2(acc[mt][nt][2], acc[mt][nt][3]);
        }
    }
}

// ---------------------------------------------------------------------------
// GEMM2: out[M,512] = data + delta @ wT.T — CTA tile 128x256, 256 threads,
// 8 warps (2M x 4N), warp tile 64x64, K-chunk 64, NCH=4, all-bf16 operands,
// 2-stage cp.async (2 x 96KB = 192KB smem). Same corrected pipeline.
// ---------------------------------------------------------------------------
static constexpr int G2_STAGE = 98304;     // Ahi16K|Alo16K|Bhi32K|Blo32K
static constexpr int G2_SMEM  = 2 * G2_STAGE;

__global__ __launch_bounds__(256, 1)
void gemm2_big(const __nv_bfloat16* __restrict__ Ahi,
               const __nv_bfloat16* __restrict__ Alo,
               const __nv_bfloat16* __restrict__ Bhi,
               const __nv_bfloat16* __restrict__ Blo,
               const float* __restrict__ Csrc,
               float* __restrict__ C)
{
    constexpr int KTOT = NCOMP_C, NOUT = NDIM_C, NCH = KTOT / 64;
    extern __shared__ char smem[];
    const uint32_t sb = smem_u32(smem);
    const int tid  = threadIdx.x;
    const int lane = tid & 31;
    const int wid  = tid >> 5;
    const int wm   = wid & 1;
    const int wn   = wid >> 1;
    const int row0 = blockIdx.y * 128;
    const int n0   = blockIdx.x * 256;

    auto issue_loads = [&](int ch, int s) {
        const uint32_t st = sb + s * G2_STAGE;
        const int k0 = ch * 64;
        #pragma unroll
        for (int i = 0; i < 4; i++) {               // A: 1024 units
            int u = i * 256 + tid;
            int r = u >> 3, u8 = (u & 7) << 3;
            uint32_t off = SWZ128((uint32_t)(r * 128 + u8 * 2));
            size_t g = (size_t)(row0 + r) * KTOT + k0 + u8;
            cp16(st + off,         Ahi + g);
            cp16(st + 16384 + off, Alo + g);
        }
        #pragma unroll
        for (int i = 0; i < 8; i++) {               // B: 2048 units
            int u = i * 256 + tid;
            int r = u >> 3, u8 = (u & 7) << 3;
            uint32_t off = SWZ128((uint32_t)(r * 128 + u8 * 2));
            size_t g = (size_t)(n0 + r) * KTOT + k0 + u8;
            cp16(st + 32768 + off, Bhi + g);
            cp16(st + 65536 + off, Blo + g);
        }
        cp_commit();
    };

    float acc[4][8][4];
    #pragma unroll
    for (int i = 0; i < 4; i++)
        #pragma unroll
        for (int j = 0; j < 8; j++)
            #pragma unroll
            for (int v = 0; v < 4; v++) acc[i][j][v] = 0.0f;

    issue_loads(0, 0);

    for (int ch = 0; ch < NCH; ch++) {
        const int s = ch & 1;
        cp_wait0();                      // exactly 1 pending group = current chunk
        __syncthreads();                 // data visible; prior-stage reads done
        if (ch + 1 < NCH) issue_loads(ch + 1, s ^ 1);

        const uint32_t st = sb + s * G2_STAGE;
        #pragma unroll
        for (int ks = 0; ks < 4; ks++) {
            const int Ck = ks * 16;
            uint32_t ah[4][4], al[4][4];
            #pragma unroll
            for (int mt = 0; mt < 4; mt++) {
                uint32_t aoff = SWZ128((uint32_t)(
                    (wm * 64 + mt * 16 + (lane & 15)) * 128 + (Ck + (lane >> 4) * 8) * 2));
                ldsm_x4(ah[mt], st + aoff);
                ldsm_x4(al[mt], st + 16384 + aoff);
            }
            #pragma unroll
            for (int p = 0; p < 4; p++) {
                uint32_t boff = SWZ128((uint32_t)(
                    (wn * 64 + p * 16 + ((lane >> 4) << 3) + (lane & 7)) * 128 +
                    (Ck + ((lane >> 3) & 1) * 8) * 2));
                uint32_t bh4[4], bl4[4];
                ldsm_x4(bh4, st + 32768 + boff);
                ldsm_x4(bl4, st + 65536 + boff);
                #pragma unroll
                for (int hf = 0; hf < 2; hf++) {
                    const int nt = 2 * p + hf;
                    const uint32_t* bh = bh4 + 2 * hf;
                    const uint32_t* bl = bl4 + 2 * hf;
                    #pragma unroll
                    for (int mt = 0; mt < 4; mt++) {
                        mma_bf16(acc[mt][nt], ah[mt], bh);
                        mma_bf16(acc[mt][nt], ah[mt], bl);
                        mma_bf16(acc[mt][nt], al[mt], bh);
                    }
                }
            }
        }
        __syncthreads();                 // stage reads done before next write
    }

    const int gr = lane >> 2;
    const int cp = (lane & 3) * 2;
    #pragma unroll
    for (int mt = 0; mt < 4; mt++) {
        #pragma unroll
        for (int nt = 0; nt < 8; nt++) {
            int row = row0 + wm * 64 + mt * 16 + gr;
            int col = n0 + wn * 64 + nt * 8 + cp;
            size_t g0 = (size_t)row * NOUT + col;
            size_t g1 = (size_t)(row + 8) * NOUT + col;
            float2 s0 = *reinterpret_cast<const float2*>(Csrc + g0);
            float2 s1 = *reinterpret_cast<const float2*>(Csrc + g1);
            *reinterpret_cast<float2*>(C + g0) =
                make_float2(acc[mt][nt][0] + s0.x, acc[mt][nt][1] + s0.y);
            *reinterpret_cast<float2*>(C + g1) =
                make_float2(acc[mt][nt][2] + s1.x, acc[mt][nt][3] + s1.y);
        }
    }
}

// ---------------------------------------------------------------------------
// Spline (R11 proven version): class-partitioned, block-per-sample, ILP-4.
// ---------------------------------------------------------------------------
static constexpr int SPLINE_SMEM = NBIN_C * NCOMP_C * 4;   // 102400

__global__ __launch_bounds__(NCOMP_C)
void spline_kernel(const float* __restrict__ x_in,
                   float* __restrict__ logj)
{
    extern __shared__ float xs[];                     // [100][256]
    __shared__ float red[32];
    const int c   = blockIdx.y;
    const int tid = threadIdx.x;
    const int lane = tid & 31, wid = tid >> 5;

    {
        const float4* src = reinterpret_cast<const float4*>(
            g_xT + (size_t)c * NBIN_C * NCOMP_C);
        float4* dst = reinterpret_cast<float4*>(xs);
        #pragma unroll
        for (int i = 0; i < 25; i++) dst[i * 256 + tid] = src[i * 256 + tid];
    }
    __syncthreads();

    const int cnt = g_cnt[c];
    const int* lst = g_list + (size_t)c * N_SAMP;
    const float4* ydp = g_ydp + (size_t)c * (NBIN_C - 1) * NCOMP_C;

    for (int i = blockIdx.x * 4; i < cnt; i += SPB * 4) {
        int nn[4];
        #pragma unroll
        for (int j = 0; j < 4; j++) nn[j] = lst[min(i + j, cnt - 1)];

        float xv[4];
        #pragma unroll
        for (int j = 0; j < 4; j++)
            xv[j] = x_in[(size_t)nn[j] * NCOMP_C + tid];

        int lo[4] = {0, 0, 0, 0}, hi[4] = {NBIN_C, NBIN_C, NBIN_C, NBIN_C};
        #pragma unroll
        for (int stp = 0; stp < 7; stp++) {
            #pragma unroll
            for (int j = 0; j < 4; j++) {
                if (lo[j] < hi[j]) {
                    int mid = (lo[j] + hi[j]) >> 1;
                    if (xs[mid * NCOMP_C + tid] < xv[j]) lo[j] = mid + 1;
                    else hi[j] = mid;
                }
            }
        }

        float ldv[4];
        #pragma unroll
        for (int j = 0; j < 4; j++) {
            const int L = lo[j];
            const int kk = (L == 0) ? 0 : ((L == NBIN_C) ? NBIN_C - 2 : L - 1);
            const float xlo = xs[kk * NCOMP_C + tid];
            const float xhi = xs[(kk + 1) * NCOMP_C + tid];
            const float4 f4 = __ldg(&ydp[(size_t)kk * NCOMP_C + tid]);
            const float x = xv[j];
            float y, ld;
            if (L == 0) {
                y = f4.x + f4.y * (x - xlo);  ld = __logf(f4.y);
            } else if (L == NBIN_C) {
                y = f4.z + f4.w * (x - xhi);  ld = __logf(f4.w);
            } else {
                float w  = xhi - xlo;
                float s  = (f4.z - f4.x) / w;
                float xi = fminf(fmaxf((x - xlo) / w, 0.0f), 1.0f);
                float xi1 = 1.0f - xi;
                float t   = xi * xi1;
                float denom = s + (f4.y + f4.w - 2.0f * s) * t;
                y = f4.x + (f4.z - f4.x) * (s * xi * xi + f4.y * t) / denom;
                float num2 = f4.w * xi * xi + 2.0f * s * t + f4.y * xi1 * xi1;
                ld = __logf(s * s * num2 / (denom * denom));
            }
            float dta = y - x;
            uint32_t h, lw;
            split_bf16(dta, h, lw);
            g_dAh[(size_t)nn[j] * NCOMP_C + tid] = __ushort_as_bfloat16((unsigned short)h);
            g_dAl[(size_t)nn[j] * NCOMP_C + tid] = __ushort_as_bfloat16((unsigned short)lw);
            ldv[j] = ld;
        }

        #pragma unroll
        for (int j = 0; j < 4; j++) {
            float v = ldv[j];
            #pragma unroll
            for (int off = 16; off; off >>= 1)
                v += __shfl_down_sync(0xffffffffu, v, off);
            if (lane == 0) red[j * 8 + wid] = v;
        }
        __syncthreads();
        if (tid < 32) {
            float v = red[tid];
            v += __shfl_down_sync(0xffffffffu, v, 4, 8);
            v += __shfl_down_sync(0xffffffffu, v, 2, 8);
            v += __shfl_down_sync(0xffffffffu, v, 1, 8);
            if      (tid == 0)  logj[nn[0]] = v;
            else if (tid == 8)  logj[nn[1]] = v;
            else if (tid == 16) logj[nn[2]] = v;
            else if (tid == 24) logj[nn[3]] = v;
        }
        __syncthreads();
    }
}

// ---------------------------------------------------------------------------
extern "C" void kernel_launch(void* const* d_in, const int* in_sizes, int n_in,
                              void* d_out, int out_size)
{
    const float* data  = (const float*)d_in[0];   // (N, 512)
    const float* wT    = (const float*)d_in[1];   // (512, 256)
    const float* kx    = (const float*)d_in[2];
    const float* ky    = (const float*)d_in[3];
    const float* kd    = (const float*)d_in[4];
    const int*   label = (const int*)d_in[5];

    float* out  = (float*)d_out;
    float* logj = out + (size_t)N_SAMP * NDIM_C;

    float* scratch = nullptr;
    cudaGetSymbolAddress((void**)&scratch, g_scratch);
    __nv_bfloat16 *dah, *dal, *bt_hi, *bt_lo, *b2_hi, *b2_lo;
    cudaGetSymbolAddress((void**)&dah, g_dAh);
    cudaGetSymbolAddress((void**)&dal, g_dAl);
    cudaGetSymbolAddress((void**)&bt_hi, g_Bt_hi);
    cudaGetSymbolAddress((void**)&bt_lo, g_Bt_lo);
    cudaGetSymbolAddress((void**)&b2_hi, g_B2_hi);
    cudaGetSymbolAddress((void**)&b2_lo, g_B2_lo);

    cudaFuncSetAttribute(gemm1_cvt,
                         cudaFuncAttributeMaxDynamicSharedMemorySize, G1_SMEM);
    cudaFuncSetAttribute(gemm2_big,
                         cudaFuncAttributeMaxDynamicSharedMemorySize, G2_SMEM);
    cudaFuncSetAttribute(spline_kernel,
                         cudaFuncAttributeMaxDynamicSharedMemorySize, SPLINE_SMEM);

    // prep
    k_prep<<<1312, 256>>>(wT, kx, ky, kd);
    k_zero<<<1, 32>>>();
    k_classify<<<N_SAMP / 256, 256>>>(label);

    // 1) data0 = data @ wT   (M=131072, N=256, K=512)
    gemm1_cvt<<<dim3(1, N_SAMP / 128), 256, G1_SMEM>>>(
        data, bt_hi, bt_lo, scratch);

    // 2) spline: delta (bf16 hi/lo) + logj
    spline_kernel<<<dim3(SPB, NCLASS_C), NCOMP_C, SPLINE_SMEM>>>(scratch, logj);

    // 3) out = data + delta @ wT.T  (M=131072, N=512, K=256)
    gemm2_big<<<dim3(NDIM_C / 256, N_SAMP / 128), 256, G2_SMEM>>>(
        dah, dal, b2_hi, b2_lo, data, out);
}